// round 8
// baseline (speedup 1.0000x reference)
#include <cuda_runtime.h>
#include <cuda_bf16.h>
#include <math.h>
#include <stdint.h>

// ---------------- problem constants ----------------
#define D_MODEL 256
#define D_FFN   1024
#define LQ      21760
#define BATCH   2
#define M_ROWS  (BATCH * LQ)   // 43520

__device__ __constant__ int c_ST[4] = {0, 16384, 20480, 21504};

// ---------------- scratch ----------------
__device__ float g_src32[(size_t)M_ROWS * D_MODEL];
__device__ float g_qsum [(size_t)M_ROWS * D_MODEL];
__device__ __nv_bfloat16 g_value[(size_t)M_ROWS * D_MODEL];
__device__ float g_oa   [(size_t)M_ROWS * 384];
__device__ float g_samp [(size_t)M_ROWS * D_MODEL];
__device__ float g_t1   [(size_t)M_ROWS * D_MODEL];
__device__ float g_h    [(size_t)M_ROWS * D_MODEL];
__device__ float g_h32  [(size_t)M_ROWS * D_MODEL];
__device__ float g_ffn  [(size_t)M_ROWS * D_FFN];
__device__ float g_t2   [(size_t)M_ROWS * D_MODEL];
__device__ float g_WvalT [256 * 256];
__device__ float g_WoaT  [384 * 256];
__device__ float g_WoutT [256 * 256];
__device__ float g_W1T   [1024 * 256];
__device__ float g_W2T   [256 * 1024];

// ---------------- helpers ----------------
__device__ __forceinline__ uint32_t smem_u32(const void* p) {
    uint32_t a;
    asm("{ .reg .u64 t; cvta.to.shared.u64 t, %1; cvt.u32.u64 %0, t; }" : "=r"(a) : "l"(p));
    return a;
}
__device__ __forceinline__ float rna_tf32(float x) {
    uint32_t u;
    asm("cvt.rna.tf32.f32 %0, %1;" : "=r"(u) : "f"(x));
    return __uint_as_float(u);
}
__device__ __forceinline__ void cpasync16(uint32_t dst, const void* src) {
    asm volatile("cp.async.cg.shared.global [%0], [%1], 16;" :: "r"(dst), "l"(src));
}
__device__ __forceinline__ void ldsm_x4(uint32_t& r0, uint32_t& r1, uint32_t& r2, uint32_t& r3, uint32_t addr) {
    asm volatile("ldmatrix.sync.aligned.m8n8.x4.shared.b16 {%0,%1,%2,%3}, [%4];"
        : "=r"(r0), "=r"(r1), "=r"(r2), "=r"(r3) : "r"(addr));
}
__device__ __forceinline__ void mma_tf32(float* d, const uint32_t* a, const uint32_t* b) {
    asm volatile("mma.sync.aligned.m16n8k8.row.col.f32.tf32.tf32.f32 "
        "{%0,%1,%2,%3}, {%4,%5,%6,%7}, {%8,%9}, {%0,%1,%2,%3};"
        : "+f"(d[0]), "+f"(d[1]), "+f"(d[2]), "+f"(d[3])
        : "r"(a[0]), "r"(a[1]), "r"(a[2]), "r"(a[3]), "r"(b[0]), "r"(b[1]));
}

// ---------------- tensor-core tf32 GEMM: BK=32, 3-stage cp.async ----------------
template <bool RESF, bool RELUF, bool ROUNDF, bool BF16OUT>
__global__ void __launch_bounds__(256) gemm_mma(
    const float* __restrict__ A, const float* __restrict__ WT,
    const float* __restrict__ bias, const float* __restrict__ bias2, int nsplit,
    const float* __restrict__ res, float* __restrict__ C, int N, int K)
{
    extern __shared__ char dynsm[];
    const uint32_t smBase = smem_u32(dynsm);

    const int tid = threadIdx.x;
    const int lane = tid & 31;
    const int wid = tid >> 5;
    const int wm = wid & 1;
    const int wn = wid >> 1;
    const int bm = blockIdx.y * 128;
    const int bn = blockIdx.x * 128;

    const float* aG[4]; const float* bG[4];
    uint32_t sOff[4];
#pragma unroll
    for (int i = 0; i < 4; i++) {
        const int id = tid + i * 256;
        const int row = id >> 3, ck = id & 7;
        aG[i] = A  + (size_t)(bm + row) * K + ck * 4;
        bG[i] = WT + (size_t)(bn + row) * K + ck * 4;
        sOff[i] = row * 128 + ((ck ^ (row & 7)) * 16);
    }

    const int lt = lane >> 3;
    const int lr = lane & 7;
    const int aRow = wm * 64 + (lt & 1) * 8 + lr;
    const int aCk0 = (lt >> 1);
    const int bRow = wn * 32 + (lt >> 1) * 8 + lr;
    const int bCk0 = (lt & 1);

    float acc[4][4][4];
#pragma unroll
    for (int i = 0; i < 4; i++)
#pragma unroll
        for (int j = 0; j < 4; j++)
#pragma unroll
            for (int k = 0; k < 4; k++) acc[i][j][k] = 0.f;

    const int Cs = K >> 5;

#pragma unroll
    for (int i = 0; i < 4; i++) {
        cpasync16(smBase + sOff[i], aG[i]);
        cpasync16(smBase + 16384 + sOff[i], bG[i]);
    }
    asm volatile("cp.async.commit_group;" ::: "memory");
#pragma unroll
    for (int i = 0; i < 4; i++) {
        cpasync16(smBase + 32768 + sOff[i], aG[i] + 32);
        cpasync16(smBase + 32768 + 16384 + sOff[i], bG[i] + 32);
    }
    asm volatile("cp.async.commit_group;" ::: "memory");

    int st = 0, ldst = 2;
    for (int c = 0; c < Cs; ++c) {
        if (c == Cs - 1) asm volatile("cp.async.wait_group 0;" ::: "memory");
        else             asm volatile("cp.async.wait_group 1;" ::: "memory");
        __syncthreads();

        const uint32_t sA = smBase + (uint32_t)st * 32768;
        const uint32_t sB = sA + 16384;

#pragma unroll
        for (int ks = 0; ks < 4; ks++) {
            uint32_t af[4][4];
            uint32_t bf[4][2];
#pragma unroll
            for (int mt = 0; mt < 4; mt++) {
                const int row = aRow + mt * 16;
                const int ck = aCk0 + ks * 2;
                ldsm_x4(af[mt][0], af[mt][1], af[mt][2], af[mt][3],
                        sA + row * 128 + ((ck ^ (row & 7)) * 16));
            }
#pragma unroll
            for (int np = 0; np < 2; np++) {
                const int row = bRow + np * 16;
                const int ck = bCk0 + ks * 2;
                uint32_t r0, r1, r2, r3;
                ldsm_x4(r0, r1, r2, r3, sB + row * 128 + ((ck ^ (row & 7)) * 16));
                bf[np * 2 + 0][0] = r0; bf[np * 2 + 0][1] = r1;
                bf[np * 2 + 1][0] = r2; bf[np * 2 + 1][1] = r3;
            }
#pragma unroll
            for (int mt = 0; mt < 4; mt++)
#pragma unroll
                for (int nt = 0; nt < 4; nt++)
                    mma_tf32(acc[mt][nt], af[mt], bf[nt]);
        }

        if (c + 2 < Cs) {
            const int k0 = (c + 2) << 5;
            const uint32_t dA = smBase + (uint32_t)ldst * 32768;
#pragma unroll
            for (int i = 0; i < 4; i++) {
                cpasync16(dA + sOff[i], aG[i] + k0);
                cpasync16(dA + 16384 + sOff[i], bG[i] + k0);
            }
            asm volatile("cp.async.commit_group;" ::: "memory");
        }
        st = (st == 2) ? 0 : st + 1;
        ldst = (ldst == 2) ? 0 : ldst + 1;
    }

    const int r0base = bm + wm * 64 + (lane >> 2);
    const int cbase  = bn + wn * 32 + (lane & 3) * 2;
#pragma unroll
    for (int mt = 0; mt < 4; mt++) {
#pragma unroll
        for (int nt = 0; nt < 4; nt++) {
            const int col = cbase + nt * 8;
            const float bx = (col < nsplit) ? bias[col] : bias2[col - nsplit];
            const float by = (col + 1 < nsplit) ? bias[col + 1] : bias2[col + 1 - nsplit];
#pragma unroll
            for (int half = 0; half < 2; half++) {
                const int row = r0base + mt * 16 + half * 8;
                float vx = acc[mt][nt][half * 2 + 0] + bx;
                float vy = acc[mt][nt][half * 2 + 1] + by;
                if (RESF) {
                    const float* rp = res + (size_t)row * N + col;
                    vx += rp[0]; vy += rp[1];
                }
                if (RELUF) { vx = fmaxf(vx, 0.f); vy = fmaxf(vy, 0.f); }
                if (ROUNDF) { vx = rna_tf32(vx); vy = rna_tf32(vy); }
                if (BF16OUT) {
                    __nv_bfloat162 bb = __floats2bfloat162_rn(vx, vy);
                    *(__nv_bfloat162*)((__nv_bfloat16*)C + (size_t)row * N + col) = bb;
                } else {
                    *(float2*)(C + (size_t)row * N + col) = make_float2(vx, vy);
                }
            }
        }
    }
}

// ---------------- prep ----------------
__global__ void __launch_bounds__(256) prep_kernel(
    const float* __restrict__ src, const float* __restrict__ pos,
    float* __restrict__ src32, float* __restrict__ qsum, int n4)
{
    int i = blockIdx.x * blockDim.x + threadIdx.x;
    if (i >= n4) return;
    float4 s = ((const float4*)src)[i];
    float4 p = ((const float4*)pos)[i];
    float4 a, q;
    a.x = rna_tf32(s.x); a.y = rna_tf32(s.y); a.z = rna_tf32(s.z); a.w = rna_tf32(s.w);
    q.x = rna_tf32(s.x + p.x); q.y = rna_tf32(s.y + p.y);
    q.z = rna_tf32(s.z + p.z); q.w = rna_tf32(s.w + p.w);
    ((float4*)src32)[i] = a;
    ((float4*)qsum)[i] = q;
}

// ---------------- fused weight transposes ----------------
__device__ __forceinline__ void tr_tile(
    const float* __restrict__ W, float* __restrict__ WT,
    int K, int N, int kt, int nt)
{
    __shared__ float tile[32][33];
    const int k0 = kt * 32, n0 = nt * 32;
    const int tx = threadIdx.x & 31, ty = threadIdx.x >> 5;
#pragma unroll
    for (int r = 0; r < 4; r++)
        tile[ty + r * 8][tx] = W[(size_t)(k0 + ty + r * 8) * N + n0 + tx];
    __syncthreads();
#pragma unroll
    for (int r = 0; r < 4; r++)
        WT[(size_t)(n0 + ty + r * 8) * K + k0 + tx] = rna_tf32(tile[tx][ty + r * 8]);
}

__global__ void __launch_bounds__(256) transpose_A(
    const float* __restrict__ Wval, const float* __restrict__ Woff,
    const float* __restrict__ Wattn, float* __restrict__ WvalT, float* __restrict__ WoaT)
{
    const int b = blockIdx.x;
    if (b < 64)       tr_tile(Wval, WvalT, 256, 256, b >> 3, b & 7);
    else if (b < 128) { const int t = b - 64;  tr_tile(Woff, WoaT, 256, 256, t >> 3, t & 7); }
    else              { const int t = b - 128; tr_tile(Wattn, WoaT + 256 * 256, 256, 128, t >> 2, t & 3); }
}

__global__ void __launch_bounds__(256) transpose_B(
    const float* __restrict__ Wout, const float* __restrict__ W1,
    const float* __restrict__ W2, float* __restrict__ WoutT,
    float* __restrict__ W1T, float* __restrict__ W2T)
{
    const int b = blockIdx.x;
    if (b < 64)       tr_tile(Wout, WoutT, 256, 256, b >> 3, b & 7);
    else if (b < 320) { const int t = b - 64;  tr_tile(W1, W1T, 256, 1024, t >> 5, t & 31); }
    else              { const int t = b - 320; tr_tile(W2, W2T, 1024, 256, t >> 3, t & 7); }
}

// ---------------- sampler: warp per (bq,h); branch-free; bf16 value ----------------
__global__ void __launch_bounds__(256) sample_bf(
    const __nv_bfloat16* __restrict__ value,  // [B*LQ, 8, 32] bf16
    const float* __restrict__ oa,
    const float* __restrict__ refp, float* __restrict__ samp)
{
    const int warp_id = (blockIdx.x * blockDim.x + threadIdx.x) >> 5;
    const int lane = threadIdx.x & 31;
    const int h  = warp_id & 7;
    const int bq = warp_id >> 3;
    const int b  = (bq >= LQ) ? 1 : 0;

    const float* al = oa + (size_t)bq * 384 + 256 + h * 16;
    float logit = (lane < 16) ? al[lane] : -1e30f;
    float mx = logit;
#pragma unroll
    for (int o = 16; o; o >>= 1) mx = fmaxf(mx, __shfl_xor_sync(0xffffffffu, mx, o));
    float e = (lane < 16) ? __expf(logit - mx) : 0.f;
    float se = e;
#pragma unroll
    for (int o = 16; o; o >>= 1) se += __shfl_xor_sync(0xffffffffu, se, o);
    const float inv_se = 1.f / se;

    float cw0, cw1, cw2, cw3;
    int ci0, ci1, ci2, ci3;
    {
        const int idx = lane & 15;
        const int lvl = idx >> 2;
        const int Ww = 128 >> lvl;
        const float fW = (float)Ww;
        const float invW = 1.f / fW;
        const int st = c_ST[lvl];

        const float* op = oa + (size_t)bq * 384 + h * 32;
        const float ox = op[idx * 2 + 0];
        const float oy = op[idx * 2 + 1];
        const float* rp = refp + (size_t)bq * 8;
        const float rx = rp[lvl * 2 + 0];
        const float ry = rp[lvl * 2 + 1];

        const float x = (rx + ox * invW) * fW - 0.5f;
        const float y = (ry + oy * invW) * fW - 0.5f;
        const float x0f = floorf(x), y0f = floorf(y);
        const int x0 = (int)x0f, y0 = (int)y0f;
        const float wx1 = x - x0f, wy1 = y - y0f;
        const float wx0 = 1.f - wx1, wy0 = 1.f - wy1;

        const float w = e * inv_se;
        const float vx0 = (x0 >= 0 && x0 < Ww) ? 1.f : 0.f;
        const float vx1 = (x0 + 1 >= 0 && x0 + 1 < Ww) ? 1.f : 0.f;
        const float vy0 = (y0 >= 0 && y0 < Ww) ? 1.f : 0.f;
        const float vy1 = (y0 + 1 >= 0 && y0 + 1 < Ww) ? 1.f : 0.f;

        cw0 = w * (wx0 * wy0) * (vx0 * vy0);
        cw1 = w * (wx1 * wy0) * (vx1 * vy0);
        cw2 = w * (wx0 * wy1) * (vx0 * vy1);
        cw3 = w * (wx1 * wy1) * (vx1 * vy1);

        const int xc0 = min(max(x0, 0), Ww - 1);
        const int xc1 = min(max(x0 + 1, 0), Ww - 1);
        const int yc0 = min(max(y0, 0), Ww - 1);
        const int yc1 = min(max(y0 + 1, 0), Ww - 1);
        ci0 = (st + yc0 * Ww + xc0) * 256;
        ci1 = (st + yc0 * Ww + xc1) * 256;
        ci2 = (st + yc1 * Ww + xc0) * 256;
        ci3 = (st + yc1 * Ww + xc1) * 256;
    }

    const __nv_bfloat16* vbase = value + (size_t)b * LQ * 256 + h * 32 + lane;
    float a0 = 0.f, a1 = 0.f, a2 = 0.f, a3 = 0.f;
#pragma unroll
    for (int p = 0; p < 16; p++) {
        const int i0 = __shfl_sync(0xffffffffu, ci0, p);
        const int i1 = __shfl_sync(0xffffffffu, ci1, p);
        const int i2 = __shfl_sync(0xffffffffu, ci2, p);
        const int i3 = __shfl_sync(0xffffffffu, ci3, p);
        const float w0 = __shfl_sync(0xffffffffu, cw0, p);
        const float w1 = __shfl_sync(0xffffffffu, cw1, p);
        const float w2 = __shfl_sync(0xffffffffu, cw2, p);
        const float w3 = __shfl_sync(0xffffffffu, cw3, p);
        a0 += w0 * __bfloat162float(__ldg(vbase + i0));
        a1 += w1 * __bfloat162float(__ldg(vbase + i1));
        a2 += w2 * __bfloat162float(__ldg(vbase + i2));
        a3 += w3 * __bfloat162float(__ldg(vbase + i3));
    }
    samp[(size_t)bq * 256 + h * 32 + lane] = rna_tf32((a0 + a1) + (a2 + a3));
}

// ---------------- layernorm: one warp per row, float4 ----------------
template <bool WR32>
__global__ void __launch_bounds__(256) ln4_kernel(
    const float* __restrict__ in, const float* __restrict__ g,
    const float* __restrict__ b, float* __restrict__ out, float* __restrict__ out32)
{
    const int lane = threadIdx.x & 31;
    const size_t row = blockIdx.x * 8 + (threadIdx.x >> 5);
    const float4* in4 = (const float4*)(in + row * 256);
    const float4 A = in4[lane * 2], B4 = in4[lane * 2 + 1];

    float s = A.x + A.y + A.z + A.w + B4.x + B4.y + B4.z + B4.w;
#pragma unroll
    for (int o = 16; o; o >>= 1) s += __shfl_xor_sync(0xffffffffu, s, o);
    const float mu = s * (1.f / 256.f);

    float4 dA, dB;
    dA.x = A.x - mu; dA.y = A.y - mu; dA.z = A.z - mu; dA.w = A.w - mu;
    dB.x = B4.x - mu; dB.y = B4.y - mu; dB.z = B4.z - mu; dB.w = B4.w - mu;
    float v = dA.x*dA.x + dA.y*dA.y + dA.z*dA.z + dA.w*dA.w
            + dB.x*dB.x + dB.y*dB.y + dB.z*dB.z + dB.w*dB.w;
#pragma unroll
    for (int o = 16; o; o >>= 1) v += __shfl_xor_sync(0xffffffffu, v, o);
    const float rstd = rsqrtf(v * (1.f / 256.f) + 1e-5f);

    const float4 gA = ((const float4*)g)[lane * 2], gB = ((const float4*)g)[lane * 2 + 1];
    const float4 bA = ((const float4*)b)[lane * 2], bB = ((const float4*)b)[lane * 2 + 1];
    float4 yA, yB;
    yA.x = dA.x * rstd * gA.x + bA.x; yA.y = dA.y * rstd * gA.y + bA.y;
    yA.z = dA.z * rstd * gA.z + bA.z; yA.w = dA.w * rstd * gA.w + bA.w;
    yB.x = dB.x * rstd * gB.x + bB.x; yB.y = dB.y * rstd * gB.y + bB.y;
    yB.z = dB.z * rstd * gB.z + bB.z; yB.w = dB.w * rstd * gB.w + bB.w;

    float4* o4 = (float4*)(out + row * 256);
    o4[lane * 2] = yA; o4[lane * 2 + 1] = yB;
    if (WR32) {
        float4 rA, rB;
        rA.x = rna_tf32(yA.x); rA.y = rna_tf32(yA.y); rA.z = rna_tf32(yA.z); rA.w = rna_tf32(yA.w);
        rB.x = rna_tf32(yB.x); rB.y = rna_tf32(yB.y); rB.z = rna_tf32(yB.z); rB.w = rna_tf32(yB.w);
        float4* r4 = (float4*)(out32 + row * 256);
        r4[lane * 2] = rA; r4[lane * 2 + 1] = rB;
    }
}

// ---------------- launch ----------------
extern "C" void kernel_launch(void* const* d_in, const int* in_sizes, int n_in,
                              void* d_out, int out_size)
{
    const float* src    = (const float*)d_in[0];
    const float* pos    = (const float*)d_in[1];
    const float* refp   = (const float*)d_in[2];
    const float* W_off  = (const float*)d_in[3];
    const float* b_off  = (const float*)d_in[4];
    const float* W_attn = (const float*)d_in[5];
    const float* b_attn = (const float*)d_in[6];
    const float* W_val  = (const float*)d_in[7];
    const float* b_val  = (const float*)d_in[8];
    const float* W_out  = (const float*)d_in[9];
    const float* b_out  = (const float*)d_in[10];
    const float* ln1_g  = (const float*)d_in[11];
    const float* ln1_b  = (const float*)d_in[12];
    const float* W1     = (const float*)d_in[13];
    const float* b1     = (const float*)d_in[14];
    const float* W2     = (const float*)d_in[15];
    const float* b2     = (const float*)d_in[16];
    const float* ln2_g  = (const float*)d_in[17];
    const float* ln2_b  = (const float*)d_in[18];
    float* out = (float*)d_out;

    float *p_src32, *p_qsum, *p_oa, *p_samp, *p_t1, *p_h, *p_h32, *p_ffn, *p_t2;
    __nv_bfloat16* p_value;
    float *p_WvalT, *p_WoaT, *p_WoutT, *p_W1T, *p_W2T;
    cudaGetSymbolAddress((void**)&p_src32, g_src32);
    cudaGetSymbolAddress((void**)&p_qsum,  g_qsum);
    cudaGetSymbolAddress((void**)&p_value, g_value);
    cudaGetSymbolAddress((void**)&p_oa,    g_oa);
    cudaGetSymbolAddress((void**)&p_samp,  g_samp);
    cudaGetSymbolAddress((void**)&p_t1,    g_t1);
    cudaGetSymbolAddress((void**)&p_h,     g_h);
    cudaGetSymbolAddress((void**)&p_h32,   g_h32);
    cudaGetSymbolAddress((void**)&p_ffn,   g_ffn);
    cudaGetSymbolAddress((void**)&p_t2,    g_t2);
    cudaGetSymbolAddress((void**)&p_WvalT, g_WvalT);
    cudaGetSymbolAddress((void**)&p_WoaT,  g_WoaT);
    cudaGetSymbolAddress((void**)&p_WoutT, g_WoutT);
    cudaGetSymbolAddress((void**)&p_W1T,   g_W1T);
    cudaGetSymbolAddress((void**)&p_W2T,   g_W2T);

    const int SMEM_BYTES = 3 * 32768;  // 96 KB
    cudaFuncSetAttribute(gemm_mma<false, false, false, true >, cudaFuncAttributeMaxDynamicSharedMemorySize, SMEM_BYTES);
    cudaFuncSetAttribute(gemm_mma<false, false, false, false>, cudaFuncAttributeMaxDynamicSharedMemorySize, SMEM_BYTES);
    cudaFuncSetAttribute(gemm_mma<true,  false, false, false>, cudaFuncAttributeMaxDynamicSharedMemorySize, SMEM_BYTES);
    cudaFuncSetAttribute(gemm_mma<false, true,  true,  false>, cudaFuncAttributeMaxDynamicSharedMemorySize, SMEM_BYTES);

    const int M = M_ROWS;
    const int MT = M / 128;  // 340
    const int BIG = 1 << 30;

    prep_kernel<<<(M * D_MODEL / 4 + 255) / 256, 256>>>(src, pos, p_src32, p_qsum, M * D_MODEL / 4);  // 0
    transpose_A<<<160, 256>>>(W_val, W_off, W_attn, p_WvalT, p_WoaT);                                  // 1
    transpose_B<<<576, 256>>>(W_out, W1, W2, p_WoutT, p_W1T, p_W2T);                                   // 2
    // value (bf16 out) = src @ W_val + b_val
    gemm_mma<false, false, false, true><<<dim3(2, MT), 256, SMEM_BYTES>>>(                              // 3
        p_src32, p_WvalT, b_val, b_val, BIG, nullptr, (float*)p_value, 256, 256);
    // oa = (src+pos) @ [W_off|W_attn] + [b_off|b_attn]
    gemm_mma<false, false, false, false><<<dim3(3, MT), 256, SMEM_BYTES>>>(                             // 4
        p_qsum, p_WoaT, b_off, b_attn, 256, nullptr, p_oa, 384, 256);
    sample_bf<<<M, 256>>>(p_value, p_oa, refp, p_samp);                                                 // 5 <- ncu
    gemm_mma<true, false, false, false><<<dim3(2, MT), 256, SMEM_BYTES>>>(                              // 6
        p_samp, p_WoutT, b_out, b_out, BIG, src, p_t1, 256, 256);
    ln4_kernel<true><<<M / 8, 256>>>(p_t1, ln1_g, ln1_b, p_h, p_h32);                                   // 7
    gemm_mma<false, true, true, false><<<dim3(8, MT), 256, SMEM_BYTES>>>(                               // 8
        p_h32, p_W1T, b1, b1, BIG, nullptr, p_ffn, 1024, 256);
    gemm_mma<true, false, false, false><<<dim3(2, MT), 256, SMEM_BYTES>>>(                              // 9
        p_ffn, p_W2T, b2, b2, BIG, p_h, p_t2, 256, 1024);
    ln4_kernel<false><<<M / 8, 256>>>(p_t2, ln2_g, ln2_b, out, nullptr);                                // 10
}

// round 9
// speedup vs baseline: 1.2624x; 1.2624x over previous
#include <cuda_runtime.h>
#include <cuda_bf16.h>
#include <math.h>
#include <stdint.h>

// ---------------- problem constants ----------------
#define D_MODEL 256
#define D_FFN   1024
#define LQ      21760
#define BATCH   2
#define M_ROWS  (BATCH * LQ)   // 43520

__device__ __constant__ int c_ST[4] = {0, 16384, 20480, 21504};

// ---------------- scratch ----------------
__device__ __nv_bfloat16 g_srcb [(size_t)M_ROWS * D_MODEL];
__device__ __nv_bfloat16 g_qsumb[(size_t)M_ROWS * D_MODEL];
__device__ __nv_bfloat16 g_value[(size_t)M_ROWS * D_MODEL];
__device__ float g_oa   [(size_t)M_ROWS * 384];
__device__ __nv_bfloat16 g_samp [(size_t)M_ROWS * D_MODEL];
__device__ float g_t1   [(size_t)M_ROWS * D_MODEL];
__device__ float g_h    [(size_t)M_ROWS * D_MODEL];
__device__ __nv_bfloat16 g_hb   [(size_t)M_ROWS * D_MODEL];
__device__ __nv_bfloat16 g_ffn  [(size_t)M_ROWS * D_FFN];
__device__ float g_t2   [(size_t)M_ROWS * D_MODEL];
__device__ __nv_bfloat16 g_WvalT [256 * 256];
__device__ __nv_bfloat16 g_WoaT  [384 * 256];
__device__ __nv_bfloat16 g_WoutT [256 * 256];
__device__ __nv_bfloat16 g_W1T   [1024 * 256];
__device__ __nv_bfloat16 g_W2T   [256 * 1024];

// ---------------- helpers ----------------
__device__ __forceinline__ uint32_t smem_u32(const void* p) {
    uint32_t a;
    asm("{ .reg .u64 t; cvta.to.shared.u64 t, %1; cvt.u32.u64 %0, t; }" : "=r"(a) : "l"(p));
    return a;
}
__device__ __forceinline__ void cpasync16(uint32_t dst, const void* src) {
    asm volatile("cp.async.cg.shared.global [%0], [%1], 16;" :: "r"(dst), "l"(src));
}
__device__ __forceinline__ void ldsm_x4(uint32_t& r0, uint32_t& r1, uint32_t& r2, uint32_t& r3, uint32_t addr) {
    asm volatile("ldmatrix.sync.aligned.m8n8.x4.shared.b16 {%0,%1,%2,%3}, [%4];"
        : "=r"(r0), "=r"(r1), "=r"(r2), "=r"(r3) : "r"(addr));
}
__device__ __forceinline__ void mma_bf16(float* d, const uint32_t* a, const uint32_t* b) {
    asm volatile("mma.sync.aligned.m16n8k16.row.col.f32.bf16.bf16.f32 "
        "{%0,%1,%2,%3}, {%4,%5,%6,%7}, {%8,%9}, {%0,%1,%2,%3};"
        : "+f"(d[0]), "+f"(d[1]), "+f"(d[2]), "+f"(d[3])
        : "r"(a[0]), "r"(a[1]), "r"(a[2]), "r"(a[3]), "r"(b[0]), "r"(b[1]));
}

// ---------------- tensor-core bf16 GEMM: BK=64, 3-stage cp.async ----------------
// stage = A 128 rows x 128B (16KB) + B 128 rows x 128B (16KB) = 32KB; 3 stages = 96KB.
// Row = 64 bf16 = 128B = 8 chunks of 16B; swizzled chunk = ck ^ (row & 7).
template <bool RESF, bool RELUF, bool BF16OUT>
__global__ void __launch_bounds__(256) gemm_mma(
    const __nv_bfloat16* __restrict__ A, const __nv_bfloat16* __restrict__ WT,
    const float* __restrict__ bias, const float* __restrict__ bias2, int nsplit,
    const float* __restrict__ res, void* __restrict__ Cout, int N, int K)
{
    extern __shared__ char dynsm[];
    const uint32_t smBase = smem_u32(dynsm);

    const int tid = threadIdx.x;
    const int lane = tid & 31;
    const int wid = tid >> 5;
    const int wm = wid & 1;
    const int wn = wid >> 1;
    const int bm = blockIdx.y * 128;
    const int bn = blockIdx.x * 128;

    // loader: 1024 chunks per operand per stage / 256 thr = 4 each
    const __nv_bfloat16* aG[4]; const __nv_bfloat16* bG[4];
    uint32_t sOff[4];
#pragma unroll
    for (int i = 0; i < 4; i++) {
        const int id = tid + i * 256;
        const int row = id >> 3, ck = id & 7;
        aG[i] = A  + (size_t)(bm + row) * K + ck * 8;
        bG[i] = WT + (size_t)(bn + row) * K + ck * 8;
        sOff[i] = row * 128 + ((ck ^ (row & 7)) * 16);
    }

    // ldmatrix lane mappings (bf16 m16n8k16)
    const int aRow = wm * 64 + (lane & 15);     // + mt*16
    const int aCkH = lane >> 4;                 // chunk hi bit
    const int bRow = wn * 32 + ((lane >> 4) & 1) * 8 + (lane & 7);  // + np*16
    const int bCkH = (lane >> 3) & 1;

    float acc[4][4][4];
#pragma unroll
    for (int i = 0; i < 4; i++)
#pragma unroll
        for (int j = 0; j < 4; j++)
#pragma unroll
            for (int k = 0; k < 4; k++) acc[i][j][k] = 0.f;

    const int Cs = K >> 6;

    // prologue: stages 0 and 1
#pragma unroll
    for (int i = 0; i < 4; i++) {
        cpasync16(smBase + sOff[i], aG[i]);
        cpasync16(smBase + 16384 + sOff[i], bG[i]);
    }
    asm volatile("cp.async.commit_group;" ::: "memory");
#pragma unroll
    for (int i = 0; i < 4; i++) {
        cpasync16(smBase + 32768 + sOff[i], aG[i] + 64);
        cpasync16(smBase + 32768 + 16384 + sOff[i], bG[i] + 64);
    }
    asm volatile("cp.async.commit_group;" ::: "memory");

    int st = 0, ldst = 2;
    for (int c = 0; c < Cs; ++c) {
        if (c == Cs - 1) asm volatile("cp.async.wait_group 0;" ::: "memory");
        else             asm volatile("cp.async.wait_group 1;" ::: "memory");
        __syncthreads();

        const uint32_t sA = smBase + (uint32_t)st * 32768;
        const uint32_t sB = sA + 16384;

#pragma unroll
        for (int ks = 0; ks < 4; ks++) {
            uint32_t af[4][4];
            uint32_t bfr[2][4];
#pragma unroll
            for (int mt = 0; mt < 4; mt++) {
                const int row = aRow + mt * 16;
                const int ck = ks * 2 + aCkH;
                ldsm_x4(af[mt][0], af[mt][1], af[mt][2], af[mt][3],
                        sA + row * 128 + ((ck ^ (row & 7)) * 16));
            }
#pragma unroll
            for (int np = 0; np < 2; np++) {
                const int row = bRow + np * 16;
                const int ck = ks * 2 + bCkH;
                ldsm_x4(bfr[np][0], bfr[np][1], bfr[np][2], bfr[np][3],
                        sB + row * 128 + ((ck ^ (row & 7)) * 16));
            }
#pragma unroll
            for (int mt = 0; mt < 4; mt++)
#pragma unroll
                for (int nt = 0; nt < 4; nt++)
                    mma_bf16(acc[mt][nt], af[mt], &bfr[nt >> 1][(nt & 1) * 2]);
        }

        if (c + 2 < Cs) {
            const int k0 = (c + 2) << 6;
            const uint32_t dA = smBase + (uint32_t)ldst * 32768;
#pragma unroll
            for (int i = 0; i < 4; i++) {
                cpasync16(dA + sOff[i], aG[i] + k0);
                cpasync16(dA + 16384 + sOff[i], bG[i] + k0);
            }
            asm volatile("cp.async.commit_group;" ::: "memory");
        }
        st = (st == 2) ? 0 : st + 1;
        ldst = (ldst == 2) ? 0 : ldst + 1;
    }

    const int r0base = bm + wm * 64 + (lane >> 2);
    const int cbase  = bn + wn * 32 + (lane & 3) * 2;
#pragma unroll
    for (int mt = 0; mt < 4; mt++) {
#pragma unroll
        for (int nt = 0; nt < 4; nt++) {
            const int col = cbase + nt * 8;
            const float bx = (col < nsplit) ? bias[col] : bias2[col - nsplit];
            const float by = (col + 1 < nsplit) ? bias[col + 1] : bias2[col + 1 - nsplit];
#pragma unroll
            for (int half = 0; half < 2; half++) {
                const int row = r0base + mt * 16 + half * 8;
                float vx = acc[mt][nt][half * 2 + 0] + bx;
                float vy = acc[mt][nt][half * 2 + 1] + by;
                if (RESF) {
                    const float* rp = res + (size_t)row * N + col;
                    vx += rp[0]; vy += rp[1];
                }
                if (RELUF) { vx = fmaxf(vx, 0.f); vy = fmaxf(vy, 0.f); }
                if (BF16OUT) {
                    __nv_bfloat162 bb = __floats2bfloat162_rn(vx, vy);
                    *(__nv_bfloat162*)((__nv_bfloat16*)Cout + (size_t)row * N + col) = bb;
                } else {
                    *(float2*)((float*)Cout + (size_t)row * N + col) = make_float2(vx, vy);
                }
            }
        }
    }
}

// ---------------- prep: bf16 src, bf16 (src+pos) ----------------
__global__ void __launch_bounds__(256) prep_kernel(
    const float* __restrict__ src, const float* __restrict__ pos,
    __nv_bfloat16* __restrict__ srcb, __nv_bfloat16* __restrict__ qsumb, int n4)
{
    int i = blockIdx.x * blockDim.x + threadIdx.x;
    if (i >= n4) return;
    float4 s = ((const float4*)src)[i];
    float4 p = ((const float4*)pos)[i];
    __nv_bfloat162* sb = (__nv_bfloat162*)srcb + i * 2;
    __nv_bfloat162* qb = (__nv_bfloat162*)qsumb + i * 2;
    sb[0] = __floats2bfloat162_rn(s.x, s.y);
    sb[1] = __floats2bfloat162_rn(s.z, s.w);
    qb[0] = __floats2bfloat162_rn(s.x + p.x, s.y + p.y);
    qb[1] = __floats2bfloat162_rn(s.z + p.z, s.w + p.w);
}

// ---------------- fused weight transposes (fp32 -> bf16) ----------------
__device__ __forceinline__ void tr_tile(
    const float* __restrict__ W, __nv_bfloat16* __restrict__ WT,
    int K, int N, int kt, int nt)
{
    __shared__ float tile[32][33];
    const int k0 = kt * 32, n0 = nt * 32;
    const int tx = threadIdx.x & 31, ty = threadIdx.x >> 5;
#pragma unroll
    for (int r = 0; r < 4; r++)
        tile[ty + r * 8][tx] = W[(size_t)(k0 + ty + r * 8) * N + n0 + tx];
    __syncthreads();
#pragma unroll
    for (int r = 0; r < 4; r++)
        WT[(size_t)(n0 + ty + r * 8) * K + k0 + tx] = __float2bfloat16_rn(tile[tx][ty + r * 8]);
}

__global__ void __launch_bounds__(256) transpose_A(
    const float* __restrict__ Wval, const float* __restrict__ Woff,
    const float* __restrict__ Wattn, __nv_bfloat16* __restrict__ WvalT,
    __nv_bfloat16* __restrict__ WoaT)
{
    const int b = blockIdx.x;
    if (b < 64)       tr_tile(Wval, WvalT, 256, 256, b >> 3, b & 7);
    else if (b < 128) { const int t = b - 64;  tr_tile(Woff, WoaT, 256, 256, t >> 3, t & 7); }
    else              { const int t = b - 128; tr_tile(Wattn, WoaT + 256 * 256, 256, 128, t >> 2, t & 3); }
}

__global__ void __launch_bounds__(256) transpose_B(
    const float* __restrict__ Wout, const float* __restrict__ W1,
    const float* __restrict__ W2, __nv_bfloat16* __restrict__ WoutT,
    __nv_bfloat16* __restrict__ W1T, __nv_bfloat16* __restrict__ W2T)
{
    const int b = blockIdx.x;
    if (b < 64)       tr_tile(Wout, WoutT, 256, 256, b >> 3, b & 7);
    else if (b < 320) { const int t = b - 64;  tr_tile(W1, W1T, 256, 1024, t >> 5, t & 31); }
    else              { const int t = b - 320; tr_tile(W2, W2T, 1024, 256, t >> 3, t & 7); }
}

// ---------------- sampler: warp per (bq,h); branch-free; bf16 value/out ----------------
__global__ void __launch_bounds__(256) sample_bf(
    const __nv_bfloat16* __restrict__ value,
    const float* __restrict__ oa,
    const float* __restrict__ refp, __nv_bfloat16* __restrict__ samp)
{
    const int warp_id = (blockIdx.x * blockDim.x + threadIdx.x) >> 5;
    const int lane = threadIdx.x & 31;
    const int h  = warp_id & 7;
    const int bq = warp_id >> 3;
    const int b  = (bq >= LQ) ? 1 : 0;

    const float* al = oa + (size_t)bq * 384 + 256 + h * 16;
    float logit = (lane < 16) ? al[lane] : -1e30f;
    float mx = logit;
#pragma unroll
    for (int o = 16; o; o >>= 1) mx = fmaxf(mx, __shfl_xor_sync(0xffffffffu, mx, o));
    float e = (lane < 16) ? __expf(logit - mx) : 0.f;
    float se = e;
#pragma unroll
    for (int o = 16; o; o >>= 1) se += __shfl_xor_sync(0xffffffffu, se, o);
    const float inv_se = 1.f / se;

    float cw0, cw1, cw2, cw3;
    int ci0, ci1, ci2, ci3;
    {
        const int idx = lane & 15;
        const int lvl = idx >> 2;
        const int Ww = 128 >> lvl;
        const float fW = (float)Ww;
        const float invW = 1.f / fW;
        const int st = c_ST[lvl];

        const float* op = oa + (size_t)bq * 384 + h * 32;
        const float ox = op[idx * 2 + 0];
        const float oy = op[idx * 2 + 1];
        const float* rp = refp + (size_t)bq * 8;
        const float rx = rp[lvl * 2 + 0];
        const float ry = rp[lvl * 2 + 1];

        const float x = (rx + ox * invW) * fW - 0.5f;
        const float y = (ry + oy * invW) * fW - 0.5f;
        const float x0f = floorf(x), y0f = floorf(y);
        const int x0 = (int)x0f, y0 = (int)y0f;
        const float wx1 = x - x0f, wy1 = y - y0f;
        const float wx0 = 1.f - wx1, wy0 = 1.f - wy1;

        const float w = e * inv_se;
        const float vx0 = (x0 >= 0 && x0 < Ww) ? 1.f : 0.f;
        const float vx1 = (x0 + 1 >= 0 && x0 + 1 < Ww) ? 1.f : 0.f;
        const float vy0 = (y0 >= 0 && y0 < Ww) ? 1.f : 0.f;
        const float vy1 = (y0 + 1 >= 0 && y0 + 1 < Ww) ? 1.f : 0.f;

        cw0 = w * (wx0 * wy0) * (vx0 * vy0);
        cw1 = w * (wx1 * wy0) * (vx1 * vy0);
        cw2 = w * (wx0 * wy1) * (vx0 * vy1);
        cw3 = w * (wx1 * wy1) * (vx1 * vy1);

        const int xc0 = min(max(x0, 0), Ww - 1);
        const int xc1 = min(max(x0 + 1, 0), Ww - 1);
        const int yc0 = min(max(y0, 0), Ww - 1);
        const int yc1 = min(max(y0 + 1, 0), Ww - 1);
        ci0 = (st + yc0 * Ww + xc0) * 256;
        ci1 = (st + yc0 * Ww + xc1) * 256;
        ci2 = (st + yc1 * Ww + xc0) * 256;
        ci3 = (st + yc1 * Ww + xc1) * 256;
    }

    const __nv_bfloat16* vbase = value + (size_t)b * LQ * 256 + h * 32 + lane;
    float a0 = 0.f, a1 = 0.f, a2 = 0.f, a3 = 0.f;
#pragma unroll
    for (int p = 0; p < 16; p++) {
        const int i0 = __shfl_sync(0xffffffffu, ci0, p);
        const int i1 = __shfl_sync(0xffffffffu, ci1, p);
        const int i2 = __shfl_sync(0xffffffffu, ci2, p);
        const int i3 = __shfl_sync(0xffffffffu, ci3, p);
        const float w0 = __shfl_sync(0xffffffffu, cw0, p);
        const float w1 = __shfl_sync(0xffffffffu, cw1, p);
        const float w2 = __shfl_sync(0xffffffffu, cw2, p);
        const float w3 = __shfl_sync(0xffffffffu, cw3, p);
        a0 += w0 * __bfloat162float(__ldg(vbase + i0));
        a1 += w1 * __bfloat162float(__ldg(vbase + i1));
        a2 += w2 * __bfloat162float(__ldg(vbase + i2));
        a3 += w3 * __bfloat162float(__ldg(vbase + i3));
    }
    samp[(size_t)bq * 256 + h * 32 + lane] = __float2bfloat16_rn((a0 + a1) + (a2 + a3));
}

// ---------------- layernorm: one warp per row, float4 ----------------
template <bool WRBF>
__global__ void __launch_bounds__(256) ln4_kernel(
    const float* __restrict__ in, const float* __restrict__ g,
    const float* __restrict__ b, float* __restrict__ out, __nv_bfloat16* __restrict__ outbf)
{
    const int lane = threadIdx.x & 31;
    const size_t row = blockIdx.x * 8 + (threadIdx.x >> 5);
    const float4* in4 = (const float4*)(in + row * 256);
    const float4 A = in4[lane * 2], B4 = in4[lane * 2 + 1];

    float s = A.x + A.y + A.z + A.w + B4.x + B4.y + B4.z + B4.w;
#pragma unroll
    for (int o = 16; o; o >>= 1) s += __shfl_xor_sync(0xffffffffu, s, o);
    const float mu = s * (1.f / 256.f);

    float4 dA, dB;
    dA.x = A.x - mu; dA.y = A.y - mu; dA.z = A.z - mu; dA.w = A.w - mu;
    dB.x = B4.x - mu; dB.y = B4.y - mu; dB.z = B4.z - mu; dB.w = B4.w - mu;
    float v = dA.x*dA.x + dA.y*dA.y + dA.z*dA.z + dA.w*dA.w
            + dB.x*dB.x + dB.y*dB.y + dB.z*dB.z + dB.w*dB.w;
#pragma unroll
    for (int o = 16; o; o >>= 1) v += __shfl_xor_sync(0xffffffffu, v, o);
    const float rstd = rsqrtf(v * (1.f / 256.f) + 1e-5f);

    const float4 gA = ((const float4*)g)[lane * 2], gB = ((const float4*)g)[lane * 2 + 1];
    const float4 bA = ((const float4*)b)[lane * 2], bB = ((const float4*)b)[lane * 2 + 1];
    float4 yA, yB;
    yA.x = dA.x * rstd * gA.x + bA.x; yA.y = dA.y * rstd * gA.y + bA.y;
    yA.z = dA.z * rstd * gA.z + bA.z; yA.w = dA.w * rstd * gA.w + bA.w;
    yB.x = dB.x * rstd * gB.x + bB.x; yB.y = dB.y * rstd * gB.y + bB.y;
    yB.z = dB.z * rstd * gB.z + bB.z; yB.w = dB.w * rstd * gB.w + bB.w;

    float4* o4 = (float4*)(out + row * 256);
    o4[lane * 2] = yA; o4[lane * 2 + 1] = yB;
    if (WRBF) {
        __nv_bfloat162* r2 = (__nv_bfloat162*)(outbf + row * 256) + lane * 4;
        r2[0] = __floats2bfloat162_rn(yA.x, yA.y);
        r2[1] = __floats2bfloat162_rn(yA.z, yA.w);
        r2[2] = __floats2bfloat162_rn(yB.x, yB.y);
        r2[3] = __floats2bfloat162_rn(yB.z, yB.w);
    }
}

// ---------------- launch ----------------
extern "C" void kernel_launch(void* const* d_in, const int* in_sizes, int n_in,
                              void* d_out, int out_size)
{
    const float* src    = (const float*)d_in[0];
    const float* pos    = (const float*)d_in[1];
    const float* refp   = (const float*)d_in[2];
    const float* W_off  = (const float*)d_in[3];
    const float* b_off  = (const float*)d_in[4];
    const float* W_attn = (const float*)d_in[5];
    const float* b_attn = (const float*)d_in[6];
    const float* W_val  = (const float*)d_in[7];
    const float* b_val  = (const float*)d_in[8];
    const float* W_out  = (const float*)d_in[9];
    const float* b_out  = (const float*)d_in[10];
    const float* ln1_g  = (const float*)d_in[11];
    const float* ln1_b  = (const float*)d_in[12];
    const float* W1     = (const float*)d_in[13];
    const float* b1     = (const float*)d_in[14];
    const float* W2     = (const float*)d_in[15];
    const float* b2     = (const float*)d_in[16];
    const float* ln2_g  = (const float*)d_in[17];
    const float* ln2_b  = (const float*)d_in[18];
    float* out = (float*)d_out;

    __nv_bfloat16 *p_srcb, *p_qsumb, *p_value, *p_samp, *p_hb, *p_ffn;
    __nv_bfloat16 *p_WvalT, *p_WoaT, *p_WoutT, *p_W1T, *p_W2T;
    float *p_oa, *p_t1, *p_h, *p_t2;
    cudaGetSymbolAddress((void**)&p_srcb,  g_srcb);
    cudaGetSymbolAddress((void**)&p_qsumb, g_qsumb);
    cudaGetSymbolAddress((void**)&p_value, g_value);
    cudaGetSymbolAddress((void**)&p_oa,    g_oa);
    cudaGetSymbolAddress((void**)&p_samp,  g_samp);
    cudaGetSymbolAddress((void**)&p_t1,    g_t1);
    cudaGetSymbolAddress((void**)&p_h,     g_h);
    cudaGetSymbolAddress((void**)&p_hb,    g_hb);
    cudaGetSymbolAddress((void**)&p_ffn,   g_ffn);
    cudaGetSymbolAddress((void**)&p_t2,    g_t2);
    cudaGetSymbolAddress((void**)&p_WvalT, g_WvalT);
    cudaGetSymbolAddress((void**)&p_WoaT,  g_WoaT);
    cudaGetSymbolAddress((void**)&p_WoutT, g_WoutT);
    cudaGetSymbolAddress((void**)&p_W1T,   g_W1T);
    cudaGetSymbolAddress((void**)&p_W2T,   g_W2T);

    const int SMEM_BYTES = 3 * 32768;  // 96 KB
    cudaFuncSetAttribute(gemm_mma<false, false, true >, cudaFuncAttributeMaxDynamicSharedMemorySize, SMEM_BYTES);
    cudaFuncSetAttribute(gemm_mma<false, false, false>, cudaFuncAttributeMaxDynamicSharedMemorySize, SMEM_BYTES);
    cudaFuncSetAttribute(gemm_mma<true,  false, false>, cudaFuncAttributeMaxDynamicSharedMemorySize, SMEM_BYTES);
    cudaFuncSetAttribute(gemm_mma<false, true,  true >, cudaFuncAttributeMaxDynamicSharedMemorySize, SMEM_BYTES);

    const int M = M_ROWS;
    const int MT = M / 128;  // 340
    const int BIG = 1 << 30;

    prep_kernel<<<(M * D_MODEL / 4 + 255) / 256, 256>>>(src, pos, p_srcb, p_qsumb, M * D_MODEL / 4);  // 0
    transpose_A<<<160, 256>>>(W_val, W_off, W_attn, p_WvalT, p_WoaT);                                  // 1
    transpose_B<<<576, 256>>>(W_out, W1, W2, p_WoutT, p_W1T, p_W2T);                                   // 2
    // value (bf16) = src @ W_val + b_val
    gemm_mma<false, false, true><<<dim3(2, MT), 256, SMEM_BYTES>>>(                                     // 3
        p_srcb, p_WvalT, b_val, b_val, BIG, nullptr, p_value, 256, 256);
    // oa (fp32) = (src+pos) @ [W_off|W_attn] + [b_off|b_attn]
    gemm_mma<false, false, false><<<dim3(3, MT), 256, SMEM_BYTES>>>(                                    // 4
        p_qsumb, p_WoaT, b_off, b_attn, 256, nullptr, p_oa, 384, 256);
    sample_bf<<<M, 256>>>(p_value, p_oa, refp, p_samp);                                                 // 5
    // t1 (fp32) = samp @ W_out + b_out + src
    gemm_mma<true, false, false><<<dim3(2, MT), 256, SMEM_BYTES>>>(                                     // 6
        p_samp, p_WoutT, b_out, b_out, BIG, src, p_t1, 256, 256);
    ln4_kernel<true><<<M / 8, 256>>>(p_t1, ln1_g, ln1_b, p_h, p_hb);                                    // 7
    // ffn (bf16) = relu(h @ W1 + b1)
    gemm_mma<false, true, true><<<dim3(8, MT), 256, SMEM_BYTES>>>(                                      // 8
        p_hb, p_W1T, b1, b1, BIG, nullptr, p_ffn, 1024, 256);
    // t2 (fp32) = ffn @ W2 + b2 + h
    gemm_mma<true, false, false><<<dim3(2, MT), 256, SMEM_BYTES>>>(                                     // 9
        p_ffn, p_W2T, b2, b2, BIG, p_h, p_t2, 256, 1024);
    ln4_kernel<false><<<M / 8, 256>>>(p_t2, ln2_g, ln2_b, out, nullptr);                                // 10
}

// round 10
// speedup vs baseline: 1.5447x; 1.2236x over previous
#include <cuda_runtime.h>
#include <cuda_bf16.h>
#include <cuda_fp16.h>
#include <math.h>
#include <stdint.h>

// ---------------- problem constants ----------------
#define D_MODEL 256
#define D_FFN   1024
#define LQ      21760
#define BATCH   2
#define M_ROWS  (BATCH * LQ)   // 43520

__device__ __constant__ int c_ST[4] = {0, 16384, 20480, 21504};

// ---------------- scratch ----------------
__device__ __nv_bfloat16 g_srcb [(size_t)M_ROWS * D_MODEL];
__device__ __nv_bfloat16 g_qsumb[(size_t)M_ROWS * D_MODEL];
__device__ __nv_bfloat16 g_value[(size_t)M_ROWS * D_MODEL];
__device__ float g_oa   [(size_t)M_ROWS * 384];
__device__ __nv_bfloat16 g_samp [(size_t)M_ROWS * D_MODEL];
__device__ float g_t1   [(size_t)M_ROWS * D_MODEL];
__device__ float g_h    [(size_t)M_ROWS * D_MODEL];
__device__ __nv_bfloat16 g_hb   [(size_t)M_ROWS * D_MODEL];
__device__ __nv_bfloat16 g_ffn  [(size_t)M_ROWS * D_FFN];
__device__ float g_t2   [(size_t)M_ROWS * D_MODEL];
__device__ __nv_bfloat16 g_WvalT [256 * 256];
__device__ __nv_bfloat16 g_WoaT  [384 * 256];
__device__ __nv_bfloat16 g_WoutT [256 * 256];
__device__ __nv_bfloat16 g_W1T   [1024 * 256];
__device__ __nv_bfloat16 g_W2T   [256 * 1024];

// ---------------- helpers ----------------
__device__ __forceinline__ uint32_t smem_u32(const void* p) {
    uint32_t a;
    asm("{ .reg .u64 t; cvta.to.shared.u64 t, %1; cvt.u32.u64 %0, t; }" : "=r"(a) : "l"(p));
    return a;
}
__device__ __forceinline__ void cpasync16(uint32_t dst, const void* src) {
    asm volatile("cp.async.cg.shared.global [%0], [%1], 16;" :: "r"(dst), "l"(src));
}
__device__ __forceinline__ void ldsm_x4(uint32_t& r0, uint32_t& r1, uint32_t& r2, uint32_t& r3, uint32_t addr) {
    asm volatile("ldmatrix.sync.aligned.m8n8.x4.shared.b16 {%0,%1,%2,%3}, [%4];"
        : "=r"(r0), "=r"(r1), "=r"(r2), "=r"(r3) : "r"(addr));
}
__device__ __forceinline__ void mma_bf16(float* d, const uint32_t* a, const uint32_t* b) {
    asm volatile("mma.sync.aligned.m16n8k16.row.col.f32.bf16.bf16.f32 "
        "{%0,%1,%2,%3}, {%4,%5,%6,%7}, {%8,%9}, {%0,%1,%2,%3};"
        : "+f"(d[0]), "+f"(d[1]), "+f"(d[2]), "+f"(d[3])
        : "r"(a[0]), "r"(a[1]), "r"(a[2]), "r"(a[3]), "r"(b[0]), "r"(b[1]));
}

// ---------------- tensor-core bf16 GEMM: BK=64, 3-stage cp.async ----------------
template <bool RESF, bool RELUF, bool BF16OUT>
__global__ void __launch_bounds__(256) gemm_mma(
    const __nv_bfloat16* __restrict__ A, const __nv_bfloat16* __restrict__ WT,
    const float* __restrict__ bias, const float* __restrict__ bias2, int nsplit,
    const float* __restrict__ res, void* __restrict__ Cout, int N, int K)
{
    extern __shared__ char dynsm[];
    const uint32_t smBase = smem_u32(dynsm);

    const int tid = threadIdx.x;
    const int lane = tid & 31;
    const int wid = tid >> 5;
    const int wm = wid & 1;
    const int wn = wid >> 1;
    const int bm = blockIdx.y * 128;
    const int bn = blockIdx.x * 128;

    const __nv_bfloat16* aG[4]; const __nv_bfloat16* bG[4];
    uint32_t sOff[4];
#pragma unroll
    for (int i = 0; i < 4; i++) {
        const int id = tid + i * 256;
        const int row = id >> 3, ck = id & 7;
        aG[i] = A  + (size_t)(bm + row) * K + ck * 8;
        bG[i] = WT + (size_t)(bn + row) * K + ck * 8;
        sOff[i] = row * 128 + ((ck ^ (row & 7)) * 16);
    }

    const int aRow = wm * 64 + (lane & 15);
    const int aCkH = lane >> 4;
    const int bRow = wn * 32 + ((lane >> 4) & 1) * 8 + (lane & 7);
    const int bCkH = (lane >> 3) & 1;

    float acc[4][4][4];
#pragma unroll
    for (int i = 0; i < 4; i++)
#pragma unroll
        for (int j = 0; j < 4; j++)
#pragma unroll
            for (int k = 0; k < 4; k++) acc[i][j][k] = 0.f;

    const int Cs = K >> 6;

#pragma unroll
    for (int i = 0; i < 4; i++) {
        cpasync16(smBase + sOff[i], aG[i]);
        cpasync16(smBase + 16384 + sOff[i], bG[i]);
    }
    asm volatile("cp.async.commit_group;" ::: "memory");
#pragma unroll
    for (int i = 0; i < 4; i++) {
        cpasync16(smBase + 32768 + sOff[i], aG[i] + 64);
        cpasync16(smBase + 32768 + 16384 + sOff[i], bG[i] + 64);
    }
    asm volatile("cp.async.commit_group;" ::: "memory");

    int st = 0, ldst = 2;
    for (int c = 0; c < Cs; ++c) {
        if (c == Cs - 1) asm volatile("cp.async.wait_group 0;" ::: "memory");
        else             asm volatile("cp.async.wait_group 1;" ::: "memory");
        __syncthreads();

        const uint32_t sA = smBase + (uint32_t)st * 32768;
        const uint32_t sB = sA + 16384;

#pragma unroll
        for (int ks = 0; ks < 4; ks++) {
            uint32_t af[4][4];
            uint32_t bfr[2][4];
#pragma unroll
            for (int mt = 0; mt < 4; mt++) {
                const int row = aRow + mt * 16;
                const int ck = ks * 2 + aCkH;
                ldsm_x4(af[mt][0], af[mt][1], af[mt][2], af[mt][3],
                        sA + row * 128 + ((ck ^ (row & 7)) * 16));
            }
#pragma unroll
            for (int np = 0; np < 2; np++) {
                const int row = bRow + np * 16;
                const int ck = ks * 2 + bCkH;
                ldsm_x4(bfr[np][0], bfr[np][1], bfr[np][2], bfr[np][3],
                        sB + row * 128 + ((ck ^ (row & 7)) * 16));
            }
#pragma unroll
            for (int mt = 0; mt < 4; mt++)
#pragma unroll
                for (int nt = 0; nt < 4; nt++)
                    mma_bf16(acc[mt][nt], af[mt], &bfr[nt >> 1][(nt & 1) * 2]);
        }

        if (c + 2 < Cs) {
            const int k0 = (c + 2) << 6;
            const uint32_t dA = smBase + (uint32_t)ldst * 32768;
#pragma unroll
            for (int i = 0; i < 4; i++) {
                cpasync16(dA + sOff[i], aG[i] + k0);
                cpasync16(dA + 16384 + sOff[i], bG[i] + k0);
            }
            asm volatile("cp.async.commit_group;" ::: "memory");
        }
        st = (st == 2) ? 0 : st + 1;
        ldst = (ldst == 2) ? 0 : ldst + 1;
    }

    const int r0base = bm + wm * 64 + (lane >> 2);
    const int cbase  = bn + wn * 32 + (lane & 3) * 2;
#pragma unroll
    for (int mt = 0; mt < 4; mt++) {
#pragma unroll
        for (int nt = 0; nt < 4; nt++) {
            const int col = cbase + nt * 8;
            const float bx = (col < nsplit) ? bias[col] : bias2[col - nsplit];
            const float by = (col + 1 < nsplit) ? bias[col + 1] : bias2[col + 1 - nsplit];
#pragma unroll
            for (int half = 0; half < 2; half++) {
                const int row = r0base + mt * 16 + half * 8;
                float vx = acc[mt][nt][half * 2 + 0] + bx;
                float vy = acc[mt][nt][half * 2 + 1] + by;
                if (RESF) {
                    const float* rp = res + (size_t)row * N + col;
                    vx += rp[0]; vy += rp[1];
                }
                if (RELUF) { vx = fmaxf(vx, 0.f); vy = fmaxf(vy, 0.f); }
                if (BF16OUT) {
                    __nv_bfloat162 bb = __floats2bfloat162_rn(vx, vy);
                    *(__nv_bfloat162*)((__nv_bfloat16*)Cout + (size_t)row * N + col) = bb;
                } else {
                    *(float2*)((float*)Cout + (size_t)row * N + col) = make_float2(vx, vy);
                }
            }
        }
    }
}

// ---------------- prep ----------------
__global__ void __launch_bounds__(256) prep_kernel(
    const float* __restrict__ src, const float* __restrict__ pos,
    __nv_bfloat16* __restrict__ srcb, __nv_bfloat16* __restrict__ qsumb, int n4)
{
    int i = blockIdx.x * blockDim.x + threadIdx.x;
    if (i >= n4) return;
    float4 s = ((const float4*)src)[i];
    float4 p = ((const float4*)pos)[i];
    __nv_bfloat162* sb = (__nv_bfloat162*)srcb + i * 2;
    __nv_bfloat162* qb = (__nv_bfloat162*)qsumb + i * 2;
    sb[0] = __floats2bfloat162_rn(s.x, s.y);
    sb[1] = __floats2bfloat162_rn(s.z, s.w);
    qb[0] = __floats2bfloat162_rn(s.x + p.x, s.y + p.y);
    qb[1] = __floats2bfloat162_rn(s.z + p.z, s.w + p.w);
}

// ---------------- fused weight transposes (fp32 -> bf16) ----------------
__device__ __forceinline__ void tr_tile(
    const float* __restrict__ W, __nv_bfloat16* __restrict__ WT,
    int K, int N, int kt, int nt)
{
    __shared__ float tile[32][33];
    const int k0 = kt * 32, n0 = nt * 32;
    const int tx = threadIdx.x & 31, ty = threadIdx.x >> 5;
#pragma unroll
    for (int r = 0; r < 4; r++)
        tile[ty + r * 8][tx] = W[(size_t)(k0 + ty + r * 8) * N + n0 + tx];
    __syncthreads();
#pragma unroll
    for (int r = 0; r < 4; r++)
        WT[(size_t)(n0 + ty + r * 8) * K + k0 + tx] = __float2bfloat16_rn(tile[tx][ty + r * 8]);
}

__global__ void __launch_bounds__(256) transpose_A(
    const float* __restrict__ Wval, const float* __restrict__ Woff,
    const float* __restrict__ Wattn, __nv_bfloat16* __restrict__ WvalT,
    __nv_bfloat16* __restrict__ WoaT)
{
    const int b = blockIdx.x;
    if (b < 64)       tr_tile(Wval, WvalT, 256, 256, b >> 3, b & 7);
    else if (b < 128) { const int t = b - 64;  tr_tile(Woff, WoaT, 256, 256, t >> 3, t & 7); }
    else              { const int t = b - 128; tr_tile(Wattn, WoaT + 256 * 256, 256, 128, t >> 2, t & 3); }
}

__global__ void __launch_bounds__(256) transpose_B(
    const float* __restrict__ Wout, const float* __restrict__ W1,
    const float* __restrict__ W2, __nv_bfloat16* __restrict__ WoutT,
    __nv_bfloat16* __restrict__ W1T, __nv_bfloat16* __restrict__ W2T)
{
    const int b = blockIdx.x;
    if (b < 64)       tr_tile(Wout, WoutT, 256, 256, b >> 3, b & 7);
    else if (b < 320) { const int t = b - 64;  tr_tile(W1, W1T, 256, 1024, t >> 5, t & 31); }
    else              { const int t = b - 320; tr_tile(W2, W2T, 1024, 256, t >> 3, t & 7); }
}

// ---------------- sampler: warp per (bq, head-pair); bf16x2 channels ----------------
// Lanes 0..15 -> head 2*hh (channels 2l,2l+1), lanes 16..31 -> head 2*hh+1.
// Per-point params packed: index = (token<<2)|dy<<1|dx ; weights = 2x half2.
__global__ void __launch_bounds__(256) sample_bf(
    const __nv_bfloat16* __restrict__ value,
    const float* __restrict__ oa,
    const float* __restrict__ refp, __nv_bfloat16* __restrict__ samp)
{
    const int warp_id = (blockIdx.x * blockDim.x + threadIdx.x) >> 5;  // over M_ROWS*4
    const int lane = threadIdx.x & 31;
    const int hh = warp_id & 3;
    const int bq = warp_id >> 2;
    const int b  = (bq >= LQ) ? 1 : 0;
    const int h  = hh * 2 + (lane >> 4);    // this half-warp's head
    const int li = lane & 15;               // point idx (param phase) / channel pair (gather)
    const int hsel = lane & 16;

    // ---- softmax over 16 logits within each half-warp ----
    const float* al = oa + (size_t)bq * 384 + 256 + h * 16;
    const float logit = al[li];
    float mx = logit;
#pragma unroll
    for (int o = 8; o; o >>= 1) mx = fmaxf(mx, __shfl_xor_sync(0xffffffffu, mx, o));
    const float e = __expf(logit - mx);
    float se = e;
#pragma unroll
    for (int o = 8; o; o >>= 1) se += __shfl_xor_sync(0xffffffffu, se, o);
    const float inv_se = 1.f / se;

    // ---- per-point params (each lane = one point of its head) ----
    int cip; uint32_t wpk01, wpk23;
    {
        const int lvl = li >> 2;
        const int Ww = 128 >> lvl;
        const float fW = (float)Ww;
        const float invW = 1.f / fW;
        const int st = c_ST[lvl];

        const float* op = oa + (size_t)bq * 384 + h * 32;
        const float ox = op[li * 2 + 0];
        const float oy = op[li * 2 + 1];
        const float* rp = refp + (size_t)bq * 8;
        const float rx = rp[lvl * 2 + 0];
        const float ry = rp[lvl * 2 + 1];

        const float x = (rx + ox * invW) * fW - 0.5f;
        const float y = (ry + oy * invW) * fW - 0.5f;
        const float x0f = floorf(x), y0f = floorf(y);
        const int x0 = (int)x0f, y0 = (int)y0f;
        const float wx1 = x - x0f, wy1 = y - y0f;
        const float wx0 = 1.f - wx1, wy0 = 1.f - wy1;

        const float w = e * inv_se;
        const float vx0 = (x0 >= 0 && x0 < Ww) ? 1.f : 0.f;
        const float vx1 = (x0 + 1 >= 0 && x0 + 1 < Ww) ? 1.f : 0.f;
        const float vy0 = (y0 >= 0 && y0 < Ww) ? 1.f : 0.f;
        const float vy1 = (y0 + 1 >= 0 && y0 + 1 < Ww) ? 1.f : 0.f;

        const float cw0 = w * (wx0 * wy0) * (vx0 * vy0);
        const float cw1 = w * (wx1 * wy0) * (vx1 * vy0);
        const float cw2 = w * (wx0 * wy1) * (vx0 * vy1);
        const float cw3 = w * (wx1 * wy1) * (vx1 * vy1);

        const int xc0 = min(max(x0, 0), Ww - 1);
        const int xc1 = min(max(x0 + 1, 0), Ww - 1);
        const int yc0 = min(max(y0, 0), Ww - 1);
        const int yc1 = min(max(y0 + 1, 0), Ww - 1);
        cip = ((st + yc0 * Ww + xc0) << 2) | ((yc1 - yc0) << 1) | (xc1 - xc0);

        __half2 ha = __floats2half2_rn(cw0, cw1);
        __half2 hb = __floats2half2_rn(cw2, cw3);
        wpk01 = *(uint32_t*)&ha;
        wpk23 = *(uint32_t*)&hb;
    }

    // ---- gather: each lane covers 2 channels (bf16x2) of its head ----
    const __nv_bfloat162* v2 = (const __nv_bfloat162*)value
        + (size_t)b * LQ * 128 + h * 16 + li;
    float ax0 = 0.f, ay0 = 0.f, ax1 = 0.f, ay1 = 0.f;
#pragma unroll
    for (int p = 0; p < 16; p++) {
        const int src = hsel | p;
        const int pk = __shfl_sync(0xffffffffu, cip, src);
        const uint32_t wa = __shfl_sync(0xffffffffu, wpk01, src);
        const uint32_t wb = __shfl_sync(0xffffffffu, wpk23, src);
        const int tok = pk >> 2;
        const int dx  = pk & 1;
        const int dyW = ((pk >> 1) & 1) * (128 >> (p >> 2));

        const __nv_bfloat162 r00 = __ldg(v2 + (size_t)tok * 128);
        const __nv_bfloat162 r10 = __ldg(v2 + (size_t)(tok + dx) * 128);
        const __nv_bfloat162 r01 = __ldg(v2 + (size_t)(tok + dyW) * 128);
        const __nv_bfloat162 r11 = __ldg(v2 + (size_t)(tok + dyW + dx) * 128);

        const float2 w01 = __half22float2(*(const __half2*)&wa);
        const float2 w23 = __half22float2(*(const __half2*)&wb);
        float2 f;
        f = __bfloat1622float2(r00); ax0 += w01.x * f.x; ay0 += w01.x * f.y;
        f = __bfloat1622float2(r10); ax1 += w01.y * f.x; ay1 += w01.y * f.y;
        f = __bfloat1622float2(r01); ax0 += w23.x * f.x; ay0 += w23.x * f.y;
        f = __bfloat1622float2(r11); ax1 += w23.y * f.x; ay1 += w23.y * f.y;
    }
    ((__nv_bfloat162*)(samp + (size_t)bq * 256 + h * 32))[li] =
        __floats2bfloat162_rn(ax0 + ax1, ay0 + ay1);
}

// ---------------- layernorm: one warp per row, float4 ----------------
template <bool WRBF>
__global__ void __launch_bounds__(256) ln4_kernel(
    const float* __restrict__ in, const float* __restrict__ g,
    const float* __restrict__ b, float* __restrict__ out, __nv_bfloat16* __restrict__ outbf)
{
    const int lane = threadIdx.x & 31;
    const size_t row = blockIdx.x * 8 + (threadIdx.x >> 5);
    const float4* in4 = (const float4*)(in + row * 256);
    const float4 A = in4[lane * 2], B4 = in4[lane * 2 + 1];

    float s = A.x + A.y + A.z + A.w + B4.x + B4.y + B4.z + B4.w;
#pragma unroll
    for (int o = 16; o; o >>= 1) s += __shfl_xor_sync(0xffffffffu, s, o);
    const float mu = s * (1.f / 256.f);

    float4 dA, dB;
    dA.x = A.x - mu; dA.y = A.y - mu; dA.z = A.z - mu; dA.w = A.w - mu;
    dB.x = B4.x - mu; dB.y = B4.y - mu; dB.z = B4.z - mu; dB.w = B4.w - mu;
    float v = dA.x*dA.x + dA.y*dA.y + dA.z*dA.z + dA.w*dA.w
            + dB.x*dB.x + dB.y*dB.y + dB.z*dB.z + dB.w*dB.w;
#pragma unroll
    for (int o = 16; o; o >>= 1) v += __shfl_xor_sync(0xffffffffu, v, o);
    const float rstd = rsqrtf(v * (1.f / 256.f) + 1e-5f);

    const float4 gA = ((const float4*)g)[lane * 2], gB = ((const float4*)g)[lane * 2 + 1];
    const float4 bA = ((const float4*)b)[lane * 2], bB = ((const float4*)b)[lane * 2 + 1];
    float4 yA, yB;
    yA.x = dA.x * rstd * gA.x + bA.x; yA.y = dA.y * rstd * gA.y + bA.y;
    yA.z = dA.z * rstd * gA.z + bA.z; yA.w = dA.w * rstd * gA.w + bA.w;
    yB.x = dB.x * rstd * gB.x + bB.x; yB.y = dB.y * rstd * gB.y + bB.y;
    yB.z = dB.z * rstd * gB.z + bB.z; yB.w = dB.w * rstd * gB.w + bB.w;

    float4* o4 = (float4*)(out + row * 256);
    o4[lane * 2] = yA; o4[lane * 2 + 1] = yB;
    if (WRBF) {
        __nv_bfloat162* r2 = (__nv_bfloat162*)(outbf + row * 256) + lane * 4;
        r2[0] = __floats2bfloat162_rn(yA.x, yA.y);
        r2[1] = __floats2bfloat162_rn(yA.z, yA.w);
        r2[2] = __floats2bfloat162_rn(yB.x, yB.y);
        r2[3] = __floats2bfloat162_rn(yB.z, yB.w);
    }
}

// ---------------- launch ----------------
extern "C" void kernel_launch(void* const* d_in, const int* in_sizes, int n_in,
                              void* d_out, int out_size)
{
    const float* src    = (const float*)d_in[0];
    const float* pos    = (const float*)d_in[1];
    const float* refp   = (const float*)d_in[2];
    const float* W_off  = (const float*)d_in[3];
    const float* b_off  = (const float*)d_in[4];
    const float* W_attn = (const float*)d_in[5];
    const float* b_attn = (const float*)d_in[6];
    const float* W_val  = (const float*)d_in[7];
    const float* b_val  = (const float*)d_in[8];
    const float* W_out  = (const float*)d_in[9];
    const float* b_out  = (const float*)d_in[10];
    const float* ln1_g  = (const float*)d_in[11];
    const float* ln1_b  = (const float*)d_in[12];
    const float* W1     = (const float*)d_in[13];
    const float* b1     = (const float*)d_in[14];
    const float* W2     = (const float*)d_in[15];
    const float* b2     = (const float*)d_in[16];
    const float* ln2_g  = (const float*)d_in[17];
    const float* ln2_b  = (const float*)d_in[18];
    float* out = (float*)d_out;

    __nv_bfloat16 *p_srcb, *p_qsumb, *p_value, *p_samp, *p_hb, *p_ffn;
    __nv_bfloat16 *p_WvalT, *p_WoaT, *p_WoutT, *p_W1T, *p_W2T;
    float *p_oa, *p_t1, *p_h, *p_t2;
    cudaGetSymbolAddress((void**)&p_srcb,  g_srcb);
    cudaGetSymbolAddress((void**)&p_qsumb, g_qsumb);
    cudaGetSymbolAddress((void**)&p_value, g_value);
    cudaGetSymbolAddress((void**)&p_oa,    g_oa);
    cudaGetSymbolAddress((void**)&p_samp,  g_samp);
    cudaGetSymbolAddress((void**)&p_t1,    g_t1);
    cudaGetSymbolAddress((void**)&p_h,     g_h);
    cudaGetSymbolAddress((void**)&p_hb,    g_hb);
    cudaGetSymbolAddress((void**)&p_ffn,   g_ffn);
    cudaGetSymbolAddress((void**)&p_t2,    g_t2);
    cudaGetSymbolAddress((void**)&p_WvalT, g_WvalT);
    cudaGetSymbolAddress((void**)&p_WoaT,  g_WoaT);
    cudaGetSymbolAddress((void**)&p_WoutT, g_WoutT);
    cudaGetSymbolAddress((void**)&p_W1T,   g_W1T);
    cudaGetSymbolAddress((void**)&p_W2T,   g_W2T);

    const int SMEM_BYTES = 3 * 32768;  // 96 KB
    cudaFuncSetAttribute(gemm_mma<false, false, true >, cudaFuncAttributeMaxDynamicSharedMemorySize, SMEM_BYTES);
    cudaFuncSetAttribute(gemm_mma<false, false, false>, cudaFuncAttributeMaxDynamicSharedMemorySize, SMEM_BYTES);
    cudaFuncSetAttribute(gemm_mma<true,  false, false>, cudaFuncAttributeMaxDynamicSharedMemorySize, SMEM_BYTES);
    cudaFuncSetAttribute(gemm_mma<false, true,  true >, cudaFuncAttributeMaxDynamicSharedMemorySize, SMEM_BYTES);

    const int M = M_ROWS;
    const int MT = M / 128;  // 340
    const int BIG = 1 << 30;

    prep_kernel<<<(M * D_MODEL / 4 + 255) / 256, 256>>>(src, pos, p_srcb, p_qsumb, M * D_MODEL / 4);  // 0
    transpose_A<<<160, 256>>>(W_val, W_off, W_attn, p_WvalT, p_WoaT);                                  // 1
    transpose_B<<<576, 256>>>(W_out, W1, W2, p_WoutT, p_W1T, p_W2T);                                   // 2
    gemm_mma<false, false, true><<<dim3(2, MT), 256, SMEM_BYTES>>>(                                     // 3
        p_srcb, p_WvalT, b_val, b_val, BIG, nullptr, p_value, 256, 256);
    gemm_mma<false, false, false><<<dim3(3, MT), 256, SMEM_BYTES>>>(                                    // 4
        p_qsumb, p_WoaT, b_off, b_attn, 256, nullptr, p_oa, 384, 256);
    sample_bf<<<M / 2, 256>>>(p_value, p_oa, refp, p_samp);                                             // 5 <- ncu
    gemm_mma<true, false, false><<<dim3(2, MT), 256, SMEM_BYTES>>>(                                     // 6
        p_samp, p_WoutT, b_out, b_out, BIG, src, p_t1, 256, 256);
    ln4_kernel<true><<<M / 8, 256>>>(p_t1, ln1_g, ln1_b, p_h, p_hb);                                    // 7
    gemm_mma<false, true, true><<<dim3(8, MT), 256, SMEM_BYTES>>>(                                      // 8
        p_hb, p_W1T, b1, b1, BIG, nullptr, p_ffn, 1024, 256);
    gemm_mma<true, false, false><<<dim3(2, MT), 256, SMEM_BYTES>>>(                                     // 9
        p_ffn, p_W2T, b2, b2, BIG, p_h, p_t2, 256, 1024);
    ln4_kernel<false><<<M / 8, 256>>>(p_t2, ln2_g, ln2_b, out, nullptr);                                // 10
}